// round 4
// baseline (speedup 1.0000x reference)
#include <cuda_runtime.h>

// Problem constants
#define BB   32
#define TT   400
#define DD   64
#define NBT  (BB*TT)      // 12800 matrices
#define S    68           // shared row stride in floats (68 % 8 == 4 -> conflict-free LDS.128)

// 0.5 * D * log(2*pi) = 32 * 1.8378770664093453
#define HALF_D_LOG_2PI 58.812066125098784f
#define EPS 1e-6f

// Scratch: per-(b,t) log-prob (no device allocation allowed -> __device__ global)
__device__ float g_partial[NBT];

// One CTA per matrix. 128 threads.
// Shared layout:
//   sm[65][68] : rows 0..63 = sigma (in-place factorization), row 64 = diff (bordered system)
//   col[68]    : staged normalized column L[.][k] each step (contiguous for broadcast float4 reads)
__global__ __launch_bounds__(128, 1)
void chol_ll_kernel(const float* __restrict__ x,
                    const float* __restrict__ mu,
                    const float* __restrict__ sigma)
{
    __shared__ __align__(16) float sm[65 * S];
    __shared__ __align__(16) float col[S];

    const int bt  = blockIdx.x;
    const int tid = threadIdx.x;

    // ---- Load sigma[bt] (64x64) coalesced via float4 ----
    const float4* src = (const float4*)(sigma + (size_t)bt * (DD * DD));
    #pragma unroll 4
    for (int idx = tid; idx < (DD * DD / 4); idx += 128) {
        float4 v = src[idx];
        int r = idx >> 4;          // row (16 float4 per row)
        int c = (idx & 15) << 2;   // col base
        *(float4*)&sm[r * S + c] = v;
    }
    // ---- Border row 64 = x - mu, and corner = 0 ----
    if (tid < DD) sm[64 * S + tid] = x[(size_t)bt * DD + tid] - mu[(size_t)bt * DD + tid];
    if (tid == 64) sm[64 * S + 64] = 0.f;

    float logdet = 0.f;
    const int r    = tid & 63;
    const int half = tid >> 6;

    // ---- Right-looking Cholesky on bordered 65x64 system ----
    for (int k = 0; k < DD; k++) {
        __syncthreads();
        // Diagonal (EPS folded in at read: element is touched only additively before this)
        float d    = sm[k * S + k] + EPS;
        float invL = rsqrtf(d);

        // Normalize column k into contiguous col[] (threads 0..63-k)
        {
            int i = k + 1 + tid;
            if (i <= 64) {
                col[i] = sm[i * S + k] * invL;
                if (i == 64) { col[65] = 0.f; col[66] = 0.f; col[67] = 0.f; }
            }
        }
        if (tid == 0) logdet += 0.5f * __logf(d);
        __syncthreads();

        // Trailing update (lower triangle + border row), 2 threads per row,
        // float4 over columns; first chunk masks j<=k by zeroing the multiplier.
        int irow = k + 1 + r;
        if (irow <= 64) {
            float v   = col[irow];
            int c0    = (k + 1) >> 2;
            int cmax  = irow >> 2;     // includes diagonal; for row 64 includes chunk 16 (corner)
            for (int c = c0 + half; c <= cmax; c += 2) {
                float4 lk = *(const float4*)&col[4 * c];
                if (c == c0) {
                    int j0 = 4 * c;
                    if (j0     <= k) lk.x = 0.f;
                    if (j0 + 1 <= k) lk.y = 0.f;
                    if (j0 + 2 <= k) lk.z = 0.f;
                    // j0+3 >= k+1 always (c0 = (k+1)>>2)
                }
                float4 a = *(float4*)&sm[irow * S + 4 * c];
                a.x = fmaf(-v, lk.x, a.x);
                a.y = fmaf(-v, lk.y, a.y);
                a.z = fmaf(-v, lk.z, a.z);
                a.w = fmaf(-v, lk.w, a.w);
                *(float4*)&sm[irow * S + 4 * c] = a;
            }
        }
    }

    __syncthreads();
    if (tid == 0) {
        // sm[64][64] = -diff^T Sigma^{-1} diff  ->  log_prob = 0.5*sm64 - logdet - C
        float lp = 0.5f * sm[64 * S + 64] - logdet - HALF_D_LOG_2PI;
        g_partial[bt] = lp;
    }
}

// Deterministic reduction: sum all log-probs in double, out = -(sum)/B
__global__ void reduce_ll_kernel(float* __restrict__ out)
{
    __shared__ double red[256];
    double acc = 0.0;
    for (int i = threadIdx.x; i < NBT; i += 256)
        acc += (double)g_partial[i];
    red[threadIdx.x] = acc;
    __syncthreads();
    #pragma unroll
    for (int sft = 128; sft > 0; sft >>= 1) {
        if (threadIdx.x < sft) red[threadIdx.x] += red[threadIdx.x + sft];
        __syncthreads();
    }
    if (threadIdx.x == 0)
        out[0] = (float)(-red[0] / (double)BB);
}

extern "C" void kernel_launch(void* const* d_in, const int* in_sizes, int n_in,
                              void* d_out, int out_size)
{
    // Identify sigma by size (B*T*D*D); the other two are x and mu.
    // (x/mu order doesn't matter: z*z is invariant under diff -> -diff.)
    const float* sigma = nullptr;
    const float* v0 = nullptr;
    const float* v1 = nullptr;
    for (int i = 0; i < n_in; i++) {
        if (in_sizes[i] == NBT * DD * DD) {
            sigma = (const float*)d_in[i];
        } else {
            if (!v0) v0 = (const float*)d_in[i];
            else     v1 = (const float*)d_in[i];
        }
    }

    chol_ll_kernel<<<NBT, 128>>>(v0, v1, sigma);
    reduce_ll_kernel<<<1, 256>>>((float*)d_out);
}

// round 8
// speedup vs baseline: 1.9504x; 1.9504x over previous
#include <cuda_runtime.h>

// Problem constants
#define BB   32
#define TT   400
#define DD   64
#define NBT  (BB*TT)      // 12800 matrices
#define S    68           // shared row stride in floats (68 % 8 == 4 -> conflict-free LDS.128)
#define NB   8            // Cholesky block size

// 0.5 * D * log(2*pi) = 32 * 1.8378770664093453
#define HALF_D_LOG_2PI 58.812066125098784f
#define EPS 1e-6f

// Scratch: per-(b,t) log-prob (no device allocation allowed -> __device__ global)
__device__ __align__(16) float g_partial[NBT];

// One CTA (128 threads) per matrix. Blocked right-looking Cholesky, NB=8,
// on the bordered 65x64 system (row 64 = x-mu, corner accumulates -z.z).
//
// Shared:
//   sm[65][S] : rows 0..63 = sigma (in-place), row 64 = diff border
//   Pt[8][S]  : transposed normalized panel, Pt[kk][i] = L[i][b0+kk]
//               (padded with zeros at i=65..67 so the border row's last
//                float4 chunk needs no masking)
__global__ __launch_bounds__(128)
void chol_ll_kernel(const float* __restrict__ x,
                    const float* __restrict__ mu,
                    const float* __restrict__ sigma)
{
    __shared__ __align__(16) float sm[65 * S];
    __shared__ __align__(16) float Pt[NB * S];

    const int bt   = blockIdx.x;
    const int tid  = threadIdx.x;
    const int lane = tid & 31;

    // ---- Load sigma[bt] (64x64) coalesced via float4 ----
    const float4* src = (const float4*)(sigma + (size_t)bt * (DD * DD));
    #pragma unroll 4
    for (int idx = tid; idx < (DD * DD / 4); idx += 128) {
        float4 v = src[idx];
        int r = idx >> 4;          // row (16 float4 per row)
        int c = (idx & 15) << 2;   // col base
        *(float4*)&sm[r * S + c] = v;
    }
    // ---- Border row 64 = x - mu, corner = 0 ----
    if (tid < DD) sm[64 * S + tid] = x[(size_t)bt * DD + tid] - mu[(size_t)bt * DD + tid];
    if (tid == 64) sm[64 * S + 64] = 0.f;

    float logdet = 0.f;   // accumulated in warp0 lane0 only

    #pragma unroll 1
    for (int b = 0; b < 8; b++) {
        const int b0 = b * NB;
        __syncthreads();   // previous trailing update (or load) complete

        // ======== Panel factorization: columns b0..b0+7, warp 0 only ========
        if (tid < 32) {
            #pragma unroll
            for (int kk = 0; kk < NB; kk++) {
                const int k = b0 + kk;
                // EPS folded at pivot read (diag only accumulates subtractions
                // before this, so (sigma_kk - S) + EPS == (sigma_kk + EPS) - S)
                float d    = sm[k * S + k] + EPS;
                float invL = rsqrtf(d);
                if (lane == 0) logdet += 0.5f * __logf(d);

                // Normalize column k into Pt[kk][*]
                for (int i = k + 1 + lane; i <= 64; i += 32)
                    Pt[kk * S + i] = sm[i * S + k] * invL;
                if (lane < 3) Pt[kk * S + 65 + lane] = 0.f;  // pad for border chunk
                __syncwarp();

                // Update remaining panel columns j = k+1 .. b0+7 (rectangle;
                // upper-junk cells within the panel are never read later)
                for (int i = k + 1 + lane; i <= 64; i += 32) {
                    float li = Pt[kk * S + i];
                    #pragma unroll
                    for (int j = k + 1; j < b0 + NB; j++)
                        sm[i * S + j] = fmaf(-li, Pt[kk * S + j], sm[i * S + j]);
                }
                __syncwarp();
            }
        }
        __syncthreads();   // panel (Pt + panel columns) visible to all warps

        // ======== Rank-8 trailing update: rows b0+8..64, cols b0+8..row ========
        const int m = 57 - b0;             // number of trailing rows
        // adaptive split: p threads per row (power of 2), p*m <= 128
        int p = 2;
        while ((m * (p << 1)) <= 128 && p < 32) p <<= 1;

        if (tid < p * m) {
            const int r = tid / p;
            const int h = tid % p;
            const int i = b0 + NB + r;

            float Li[NB];
            #pragma unroll
            for (int kk = 0; kk < NB; kk++) Li[kk] = Pt[kk * S + i];

            const int c0   = (b0 + NB) >> 2;   // first float4 chunk (8-aligned cols)
            const int cend = i >> 2;           // includes diag chunk (junk above diag
                                               // is written but never read)
            for (int c = c0 + h; c <= cend; c += p) {
                float4 a = *(float4*)&sm[i * S + 4 * c];
                #pragma unroll
                for (int kk = 0; kk < NB; kk++) {
                    float4 pk = *(const float4*)&Pt[kk * S + 4 * c];
                    a.x = fmaf(-Li[kk], pk.x, a.x);
                    a.y = fmaf(-Li[kk], pk.y, a.y);
                    a.z = fmaf(-Li[kk], pk.z, a.z);
                    a.w = fmaf(-Li[kk], pk.w, a.w);
                }
                *(float4*)&sm[i * S + 4 * c] = a;
            }
        }
    }

    __syncthreads();
    if (tid == 0) {
        // sm[64][64] = -diff^T Sigma^{-1} diff
        float lp = 0.5f * sm[64 * S + 64] - logdet - HALF_D_LOG_2PI;
        g_partial[bt] = lp;
    }
}

// Deterministic reduction in double: out = -(sum)/B
__global__ void reduce_ll_kernel(float* __restrict__ out)
{
    __shared__ double red[1024];
    double acc = 0.0;
    const float4* p = (const float4*)g_partial;
    for (int i = threadIdx.x; i < NBT / 4; i += 1024) {
        float4 v = p[i];
        acc += (double)v.x + (double)v.y + (double)v.z + (double)v.w;
    }
    red[threadIdx.x] = acc;
    __syncthreads();
    #pragma unroll
    for (int s = 512; s > 0; s >>= 1) {
        if (threadIdx.x < s) red[threadIdx.x] += red[threadIdx.x + s];
        __syncthreads();
    }
    if (threadIdx.x == 0)
        out[0] = (float)(-red[0] / (double)BB);
}

extern "C" void kernel_launch(void* const* d_in, const int* in_sizes, int n_in,
                              void* d_out, int out_size)
{
    // Identify sigma by size (B*T*D*D); the other two are x and mu.
    // (x/mu order doesn't matter: z*z is invariant under diff -> -diff.)
    const float* sigma = nullptr;
    const float* v0 = nullptr;
    const float* v1 = nullptr;
    for (int i = 0; i < n_in; i++) {
        if (in_sizes[i] == NBT * DD * DD) {
            sigma = (const float*)d_in[i];
        } else {
            if (!v0) v0 = (const float*)d_in[i];
            else     v1 = (const float*)d_in[i];
        }
    }

    chol_ll_kernel<<<NBT, 128>>>(v0, v1, sigma);
    reduce_ll_kernel<<<1, 1024>>>((float*)d_out);
}